// round 14
// baseline (speedup 1.0000x reference)
#include <cuda_runtime.h>
#include <math.h>

#define N     8192
#define D     256
#define H     512
#define KP    64
#define NT    17
#define NSLOT (KP*NT)       // 1088
#define INV_TAU 20.0f
#define KLF  (1.0f/1.05f)
#define SITERS 50
#define CSIZE 8
#define MAXCHUNK 96
#define NBH   32            // histogram blocks (N/256)

// ---------------- scratch ----------------
__device__ float g_h[N*H];
__device__ float g_Mp[N*KP];      // M = -d2/tau, rows permuted by type (for k_out)
__device__ float g_up[N];
__device__ float g_lv[NT*KP];
__device__ int   g_start[NT+1];
__device__ int   g_perm[N];
__device__ int   g_pos[N];
__device__ int   g_bh[NBH*NT];    // per-block type histograms

// ---------------- packed f32x2 helpers (FFMA2: 2 FMA/lane/issue) ----------------
#define BCAST2(dst, x)     asm("mov.b64 %0, {%1, %1};" : "=l"(dst) : "f"(x))
#define FFMA2(c, a, b)     asm("fma.rn.f32x2 %0, %1, %2, %0;" : "+l"(c) : "l"(a), "l"(b))
#define UNPACK2(lo, hi, s) asm("mov.b64 {%0, %1}, %2;" : "=f"(lo), "=f"(hi) : "l"(s))

__device__ __forceinline__ unsigned smem_u32(const void* p) {
    unsigned a;
    asm("{ .reg .u64 t; cvta.to.shared.u64 t, %1; cvt.u32.u64 %0, t; }" : "=r"(a) : "l"(p));
    return a;
}
__device__ __forceinline__ float dsmem_ldf(unsigned laddr, unsigned rank) {
    unsigned r; float v;
    asm volatile("mapa.shared::cluster.u32 %0, %1, %2;" : "=r"(r) : "r"(laddr), "r"(rank));
    asm volatile("ld.shared::cluster.f32 %0, [%1];" : "=f"(v) : "r"(r));
    return v;
}

// ---------------- parallel stable counting sort (2 kernels) ---------------------
__global__ void p_hist(const int* __restrict__ jt) {
    __shared__ int h[8][NT];
    int tid = threadIdx.x, w = tid >> 5, lane = tid & 31, b = blockIdx.x;
    if (tid < 8 * NT) ((int*)h)[tid] = 0;
    __syncthreads();
    int t = jt[b * 256 + tid];
    unsigned mask = __match_any_sync(0xffffffffu, t);
    int rnk = __popc(mask & ((1u << lane) - 1u));
    if (rnk == 0) h[w][t] = __popc(mask);
    __syncthreads();
    if (tid < NT) {
        int s = 0;
#pragma unroll
        for (int ww = 0; ww < 8; ww++) s += h[ww][tid];
        g_bh[b * NT + tid] = s;
    }
}

__global__ void p_scatter(const int* __restrict__ jt) {
    __shared__ int cnt[NT];
    __shared__ int sstart[NT];
    __shared__ int soff[NT];
    __shared__ int h[8][NT];
    __shared__ int off[8][NT];
    int tid = threadIdx.x, w = tid >> 5, lane = tid & 31, b = blockIdx.x;
    if (tid < 8 * NT) ((int*)h)[tid] = 0;
    if (tid < NT) {
        int s = 0;
        for (int bb = 0; bb < NBH; bb++) s += g_bh[bb * NT + tid];
        cnt[tid] = s;
    }
    __syncthreads();
    if (tid == 0) {
        int s = 0;
        for (int t = 0; t < NT; t++) { sstart[t] = s; s += cnt[t]; }
        if (b == 0) {
            for (int t = 0; t < NT; t++) g_start[t] = sstart[t];
            g_start[NT] = s;
        }
    }
    __syncthreads();
    if (tid < NT) {
        int run = sstart[tid];
        for (int bb = 0; bb < b; bb++) run += g_bh[bb * NT + tid];
        soff[tid] = run;
    }
    int n = b * 256 + tid;
    int t = jt[n];
    unsigned mask = __match_any_sync(0xffffffffu, t);
    int rnk = __popc(mask & ((1u << lane) - 1u));
    if (rnk == 0) h[w][t] = __popc(mask);
    __syncthreads();
    if (tid < NT) {
        int run = soff[tid];
#pragma unroll
        for (int ww = 0; ww < 8; ww++) { off[ww][tid] = run; run += h[ww][tid]; }
    }
    __syncthreads();
    int pos = off[w][t] + rnk;
    g_perm[pos] = n;
    g_pos[n]  = pos;
}

// ---------------- GEMM1: h = selu(emb @ W1 + b1), f32x2 + sw pipeline -----------
__global__ void __launch_bounds__(512) k_gemm1(const float* __restrict__ A,
                                               const float* __restrict__ W,
                                               const float* __restrict__ bias) {
    __shared__ __align__(16) float As[16][260];   // k-major (row pairs adjacent)
    __shared__ __align__(16) float Bs[16][132];
    __shared__ float sb[128];
    int bm = blockIdx.x * 256, bn = blockIdx.y * 128;
    int tid = threadIdx.x;
    int w = tid >> 5, lane = tid & 31;
    int ty = ((w & 7) << 2) | (lane >> 3);   // 0..31
    int tx = ((w >> 3) << 3) | (lane & 7);   // 0..15
    if (tid < 128) sb[tid] = bias[bn + tid];

    int ar0 = tid >> 2,         ac4_0 = tid & 3;
    int ar1 = (tid + 512) >> 2, ac4_1 = tid & 3;
    int bk  = tid >> 5,         bn4   = tid & 31;

    unsigned long long acc[4][8];
#pragma unroll
    for (int i = 0; i < 4; i++)
#pragma unroll
        for (int j = 0; j < 8; j++) acc[i][j] = 0ULL;

    float4 pa0 = *(const float4*)&A[(bm + ar0) * D + ac4_0 * 4];
    float4 pa1 = *(const float4*)&A[(bm + ar1) * D + ac4_1 * 4];
    float4 pbv = *(const float4*)&W[bk * H + bn + bn4 * 4];

    for (int k0 = 0; k0 < D; k0 += 16) {
        As[ac4_0 * 4 + 0][ar0] = pa0.x; As[ac4_0 * 4 + 1][ar0] = pa0.y;
        As[ac4_0 * 4 + 2][ar0] = pa0.z; As[ac4_0 * 4 + 3][ar0] = pa0.w;
        As[ac4_1 * 4 + 0][ar1] = pa1.x; As[ac4_1 * 4 + 1][ar1] = pa1.y;
        As[ac4_1 * 4 + 2][ar1] = pa1.z; As[ac4_1 * 4 + 3][ar1] = pa1.w;
        *(float4*)&Bs[bk][bn4 * 4] = pbv;
        __syncthreads();

        if (k0 + 16 < D) {
            pa0 = *(const float4*)&A[(bm + ar0) * D + k0 + 16 + ac4_0 * 4];
            pa1 = *(const float4*)&A[(bm + ar1) * D + k0 + 16 + ac4_1 * 4];
            pbv = *(const float4*)&W[(k0 + 16 + bk) * H + bn + bn4 * 4];
        }

#pragma unroll
        for (int kk = 0; kk < 16; kk++) {
            ulonglong2 a01 = *(const ulonglong2*)&As[kk][ty * 8];
            ulonglong2 a23 = *(const ulonglong2*)&As[kk][ty * 8 + 4];
            float4 b0 = *(const float4*)&Bs[kk][tx * 8];
            float4 b1 = *(const float4*)&Bs[kk][tx * 8 + 4];
            unsigned long long ap[4] = {a01.x, a01.y, a23.x, a23.y};
            unsigned long long bb[8];
            float bf[8] = {b0.x, b0.y, b0.z, b0.w, b1.x, b1.y, b1.z, b1.w};
#pragma unroll
            for (int j = 0; j < 8; j++) BCAST2(bb[j], bf[j]);
#pragma unroll
            for (int pi = 0; pi < 4; pi++)
#pragma unroll
                for (int j = 0; j < 8; j++) FFMA2(acc[pi][j], ap[pi], bb[j]);
        }
        __syncthreads();
    }
    const float SC = 1.0507009873554805f;
    const float AL = 1.6732632423543772f;
#pragma unroll
    for (int pi = 0; pi < 4; pi++) {
        float o0[8], o1[8];
#pragma unroll
        for (int j = 0; j < 8; j++) {
            float x0, x1;
            UNPACK2(x0, x1, acc[pi][j]);
            x0 += sb[tx * 8 + j];
            x1 += sb[tx * 8 + j];
            o0[j] = (x0 > 0.f) ? SC * x0 : SC * AL * expm1f(x0);
            o1[j] = (x1 > 0.f) ? SC * x1 : SC * AL * expm1f(x1);
        }
        int row0 = bm + ty * 8 + pi * 2;
        *(float4*)&g_h[row0 * H + bn + tx * 8]           = make_float4(o0[0], o0[1], o0[2], o0[3]);
        *(float4*)&g_h[row0 * H + bn + tx * 8 + 4]       = make_float4(o0[4], o0[5], o0[6], o0[7]);
        *(float4*)&g_h[(row0 + 1) * H + bn + tx * 8]     = make_float4(o1[0], o1[1], o1[2], o1[3]);
        *(float4*)&g_h[(row0 + 1) * H + bn + tx * 8 + 4] = make_float4(o1[4], o1[5], o1[6], o1[7]);
    }
}

// ---------------- Sinkhorn with FUSED M-slice GEMM ------------------------------
// 17 types x 8-CTA clusters, 256 threads. Each CTA computes its own <=96x64
// M-slice from g_h (gathered rows) + proto, then iterates. sM aliases the
// GEMM scratch (Hs/Ps) -- scratch reads all complete before sM writes.
__global__ void __cluster_dims__(CSIZE, 1, 1) __launch_bounds__(256)
k_sinkhorn(const float* __restrict__ proto) {
    __shared__ __align__(16) float sbuf[MAXCHUNK * 65];   // 6240 floats
    __shared__ float su[MAXCHUNK];
    __shared__ float slv[KP];
    __shared__ float shn[MAXCHUNK];
    __shared__ float spn[KP];
    __shared__ float wmx[4][KP], wse[4][KP];
    __shared__ float pmx[2][KP], pse[2][KP];
    __shared__ int   pr[MAXCHUNK];

    int t    = blockIdx.x >> 3;
    int rank = blockIdx.x & 7;
    int s = g_start[t];
    int c = g_start[t + 1] - s;
    int chunk = (c + CSIZE - 1) >> 3;
    int r0 = rank * chunk;
    int cn = c - r0;
    if (cn < 0) cn = 0;
    if (cn > chunk) cn = chunk;
    int tid = threadIdx.x, w = tid >> 5, lane = tid & 31;
    int ty = tid >> 4, tx = tid & 15;

    // ---- phase 0: perm gather table (clamped so all 96 GEMM rows read valid mem)
    if (tid < MAXCHUNK) pr[tid] = (tid < cn) ? g_perm[s + r0 + tid] : g_perm[s];
    if (tid < KP) slv[tid] = 0.f;
    __syncthreads();

    // ---- phase 1: fused GEMM  (Hs: [32][100] at sbuf[0], Ps: [32][68] at sbuf[3200])
    float* Hs = sbuf;           // stride 100
    float* Ps = sbuf + 3200;    // stride 68
    int hc4 = tid & 7;
    int hrow0 = tid >> 3, hrow1 = hrow0 + 32, hrow2 = hrow0 + 64;   // H loader rows
    int prow0 = hrow0, prow1 = hrow0 + 32;                          // P loader rows

    unsigned long long acc[3][4];
#pragma unroll
    for (int i = 0; i < 3; i++)
#pragma unroll
        for (int j = 0; j < 4; j++) acc[i][j] = 0ULL;
    float hnp0 = 0.f, hnp1 = 0.f, hnp2 = 0.f, pnp0 = 0.f, pnp1 = 0.f;

    for (int j0 = 0; j0 < H; j0 += 32) {
        {
            float4 v = *(const float4*)&g_h[pr[hrow0] * H + j0 + hc4 * 4];
            Hs[(hc4 * 4 + 0) * 100 + hrow0] = v.x; Hs[(hc4 * 4 + 1) * 100 + hrow0] = v.y;
            Hs[(hc4 * 4 + 2) * 100 + hrow0] = v.z; Hs[(hc4 * 4 + 3) * 100 + hrow0] = v.w;
            hnp0 += v.x * v.x + v.y * v.y + v.z * v.z + v.w * v.w;
            float4 u = *(const float4*)&g_h[pr[hrow1] * H + j0 + hc4 * 4];
            Hs[(hc4 * 4 + 0) * 100 + hrow1] = u.x; Hs[(hc4 * 4 + 1) * 100 + hrow1] = u.y;
            Hs[(hc4 * 4 + 2) * 100 + hrow1] = u.z; Hs[(hc4 * 4 + 3) * 100 + hrow1] = u.w;
            hnp1 += u.x * u.x + u.y * u.y + u.z * u.z + u.w * u.w;
            float4 x = *(const float4*)&g_h[pr[hrow2] * H + j0 + hc4 * 4];
            Hs[(hc4 * 4 + 0) * 100 + hrow2] = x.x; Hs[(hc4 * 4 + 1) * 100 + hrow2] = x.y;
            Hs[(hc4 * 4 + 2) * 100 + hrow2] = x.z; Hs[(hc4 * 4 + 3) * 100 + hrow2] = x.w;
            hnp2 += x.x * x.x + x.y * x.y + x.z * x.z + x.w * x.w;
        }
        {
            float4 v = *(const float4*)&proto[prow0 * H + j0 + hc4 * 4];
            Ps[(hc4 * 4 + 0) * 68 + prow0] = v.x; Ps[(hc4 * 4 + 1) * 68 + prow0] = v.y;
            Ps[(hc4 * 4 + 2) * 68 + prow0] = v.z; Ps[(hc4 * 4 + 3) * 68 + prow0] = v.w;
            pnp0 += v.x * v.x + v.y * v.y + v.z * v.z + v.w * v.w;
            float4 u = *(const float4*)&proto[prow1 * H + j0 + hc4 * 4];
            Ps[(hc4 * 4 + 0) * 68 + prow1] = u.x; Ps[(hc4 * 4 + 1) * 68 + prow1] = u.y;
            Ps[(hc4 * 4 + 2) * 68 + prow1] = u.z; Ps[(hc4 * 4 + 3) * 68 + prow1] = u.w;
            pnp1 += u.x * u.x + u.y * u.y + u.z * u.z + u.w * u.w;
        }
        __syncthreads();
#pragma unroll
        for (int kk = 0; kk < 32; kk++) {
            const float* hk = &Hs[kk * 100];
            const float* pk = &Ps[kk * 68];
            unsigned long long ap[3];
            ap[0] = *(const unsigned long long*)&hk[ty * 6];
            ap[1] = *(const unsigned long long*)&hk[ty * 6 + 2];
            ap[2] = *(const unsigned long long*)&hk[ty * 6 + 4];
            float4 b = *(const float4*)&pk[tx * 4];
            unsigned long long bb[4];
            BCAST2(bb[0], b.x); BCAST2(bb[1], b.y);
            BCAST2(bb[2], b.z); BCAST2(bb[3], b.w);
#pragma unroll
            for (int pi = 0; pi < 3; pi++)
#pragma unroll
                for (int j = 0; j < 4; j++) FFMA2(acc[pi][j], ap[pi], bb[j]);
        }
        __syncthreads();
    }
    // norm reductions across 8 loader-column threads (consecutive tids)
#pragma unroll
    for (int o = 1; o < 8; o <<= 1) {
        hnp0 += __shfl_xor_sync(0xffffffffu, hnp0, o);
        hnp1 += __shfl_xor_sync(0xffffffffu, hnp1, o);
        hnp2 += __shfl_xor_sync(0xffffffffu, hnp2, o);
        pnp0 += __shfl_xor_sync(0xffffffffu, pnp0, o);
        pnp1 += __shfl_xor_sync(0xffffffffu, pnp1, o);
    }
    if (hc4 == 0) {
        shn[hrow0] = hnp0; shn[hrow1] = hnp1; shn[hrow2] = hnp2;
        spn[prow0] = pnp0; spn[prow1] = pnp1;
    }
    __syncthreads();   // norms ready AND all Hs/Ps reads done -> sM may overwrite

    // ---- phase 2: finalize M into sM (aliases scratch)
    float* sM = sbuf;  // stride 65
#pragma unroll
    for (int pi = 0; pi < 3; pi++) {
        float c0[4], c1[4];
#pragma unroll
        for (int j = 0; j < 4; j++) UNPACK2(c0[j], c1[j], acc[pi][j]);
        int rr = ty * 6 + pi * 2;
        float hnA = shn[rr], hnB = shn[rr + 1];
#pragma unroll
        for (int j = 0; j < 4; j++) {
            float pnv = spn[tx * 4 + j];
            sM[rr * 65 + tx * 4 + j]       = -INV_TAU * fmaxf(hnA + pnv - 2.f * c0[j], 0.f);
            sM[(rr + 1) * 65 + tx * 4 + j] = -INV_TAU * fmaxf(hnB + pnv - 2.f * c1[j], 0.f);
        }
    }
    __syncthreads();

    // ---- phase 3: Sinkhorn iterations (identical to proven R12 code)
    int q = (cn + 3) >> 2;
    int sub = tid & 3;
    unsigned gmask = 0xFu << (tid & 28);
    int col = ((w & 1) << 5) + lane;
    int rs_ = (w >> 1) * q;
    int re_ = min(cn, rs_ + q);
    int nr  = re_ - rs_;

    for (int it = 0; it < SITERS; it++) {
        float lvr[16];
#pragma unroll
        for (int j = 0; j < 16; j++) lvr[j] = slv[sub * 16 + j];
        for (int r = tid >> 2; r < cn; r += 64) {
            const float* row = &sM[r * 65 + sub * 16];
            float v[16];
            float m0 = -3.4e38f, m1 = -3.4e38f, m2 = -3.4e38f, m3 = -3.4e38f;
#pragma unroll
            for (int j = 0; j < 16; j += 4) {
                v[j]   = row[j]   + lvr[j];   m0 = fmaxf(m0, v[j]);
                v[j+1] = row[j+1] + lvr[j+1]; m1 = fmaxf(m1, v[j+1]);
                v[j+2] = row[j+2] + lvr[j+2]; m2 = fmaxf(m2, v[j+2]);
                v[j+3] = row[j+3] + lvr[j+3]; m3 = fmaxf(m3, v[j+3]);
            }
            float mx = fmaxf(fmaxf(m0, m1), fmaxf(m2, m3));
            mx = fmaxf(mx, __shfl_xor_sync(gmask, mx, 1));
            mx = fmaxf(mx, __shfl_xor_sync(gmask, mx, 2));
            float s0 = 0.f, s1 = 0.f, s2 = 0.f, s3 = 0.f;
#pragma unroll
            for (int j = 0; j < 16; j += 4) {
                s0 += __expf(v[j]   - mx);
                s1 += __expf(v[j+1] - mx);
                s2 += __expf(v[j+2] - mx);
                s3 += __expf(v[j+3] - mx);
            }
            float se = (s0 + s1) + (s2 + s3);
            se += __shfl_xor_sync(gmask, se, 1);
            se += __shfl_xor_sync(gmask, se, 2);
            if (sub == 0) su[r] = -(mx + __logf(se));
        }
        __syncthreads();

        {
            float v[24];
            float m0 = -3.4e38f, m1 = -3.4e38f, m2 = -3.4e38f, m3 = -3.4e38f;
#pragma unroll
            for (int i = 0; i < 24; i++) {
                if (i >= nr) break;
                v[i] = sM[(rs_ + i) * 65 + col] + su[rs_ + i];
                if ((i & 3) == 0) m0 = fmaxf(m0, v[i]);
                else if ((i & 3) == 1) m1 = fmaxf(m1, v[i]);
                else if ((i & 3) == 2) m2 = fmaxf(m2, v[i]);
                else m3 = fmaxf(m3, v[i]);
            }
            float mx = fmaxf(fmaxf(m0, m1), fmaxf(m2, m3));
            float s0 = 0.f, s1 = 0.f, s2 = 0.f, s3 = 0.f;
#pragma unroll
            for (int i = 0; i < 24; i++) {
                if (i >= nr) break;
                float e = __expf(v[i] - mx);
                if ((i & 3) == 0) s0 += e;
                else if ((i & 3) == 1) s1 += e;
                else if ((i & 3) == 2) s2 += e;
                else s3 += e;
            }
            wmx[w >> 1][col] = mx;
            wse[w >> 1][col] = (s0 + s1) + (s2 + s3);
        }
        __syncthreads();
        int par = it & 1;
        if (tid < KP) {
            float mx = fmaxf(fmaxf(wmx[0][tid], wmx[1][tid]), fmaxf(wmx[2][tid], wmx[3][tid]));
            float se = 0.f;
#pragma unroll
            for (int i = 0; i < 4; i++) se += wse[i][tid] * __expf(wmx[i][tid] - mx);
            pmx[par][tid] = mx;
            pse[par][tid] = se;
        }

        asm volatile("barrier.cluster.arrive.aligned;" ::: "memory");
        asm volatile("barrier.cluster.wait.aligned;" ::: "memory");

        if (tid < KP) {
            unsigned amx = smem_u32(&pmx[par][tid]);
            unsigned ase = smem_u32(&pse[par][tid]);
            float m[CSIZE], sv[CSIZE];
            float MX = -3.4e38f;
#pragma unroll
            for (int rk = 0; rk < CSIZE; rk++) {
                m[rk]  = dsmem_ldf(amx, rk);
                sv[rk] = dsmem_ldf(ase, rk);
                MX = fmaxf(MX, m[rk]);
            }
            float SE = 0.f;
#pragma unroll
            for (int rk = 0; rk < CSIZE; rk++) SE += sv[rk] * __expf(m[rk] - MX);
            slv[tid] = -KLF * (MX + __logf(SE));
        }
        __syncthreads();
    }

    // ---- phase 4: outputs (g_up, g_lv, and writeback sM -> g_Mp for k_out)
    if (tid < cn) g_up[s + r0 + tid] = su[tid];
    if (rank == 0 && tid < KP) g_lv[t * KP + tid] = slv[tid];
    for (int idx = tid; idx < cn * KP; idx += 256) {
        int r = idx >> 6, cc = idx & 63;
        g_Mp[(s + r0 + r) * KP + cc] = sM[r * 65 + cc];
    }

    // no CTA may exit while a peer might still read its smem (final combine)
    asm volatile("barrier.cluster.arrive.aligned;" ::: "memory");
    asm volatile("barrier.cluster.wait.aligned;" ::: "memory");
}

// ---------------- fused output: T (float4 coalesced) + logits -------------------
__global__ void k_out(const int* __restrict__ jt, float* __restrict__ out) {
    int idx4 = blockIdx.x * blockDim.x + threadIdx.x;   // over N*NSLOT/4
    int base = idx4 * 4;
    int n = base / NSLOT;
    int s0 = base - n * NSLOT;
    int tn = jt[n];
    int p = g_pos[n];
    float up = g_up[p];
    float e[4] = {0.f, 0.f, 0.f, 0.f};
#pragma unroll
    for (int q = 0; q < 4; q++) {
        int slot = s0 + q;
        int k = slot / NT;
        int t = slot - k * NT;
        if (t == tn) {
            float ev = __expf(g_Mp[p * KP + k] + up + g_lv[tn * KP + k]);
            e[q] = ev;
            out[n * KP + k] = __logf(ev + 1e-8f);
        }
    }
    *(float4*)&out[N * KP + base] = make_float4(e[0], e[1], e[2], e[3]);
}

__global__ void k_out_logits(const int* __restrict__ jt, float* __restrict__ out) {
    int idx = blockIdx.x * blockDim.x + threadIdx.x;   // over N*KP
    if (idx >= N * KP) return;
    int n = idx >> 6, k = idx & 63;
    int tn = jt[n];
    int p = g_pos[n];
    float e = __expf(g_Mp[p * KP + k] + g_up[p] + g_lv[tn * KP + k]);
    out[n * KP + k] = __logf(e + 1e-8f);
}

// ---------------- launch --------------------------------------------------------
extern "C" void kernel_launch(void* const* d_in, const int* in_sizes, int n_in,
                              void* d_out, int out_size) {
    const float* emb   = (const float*)d_in[0];
    const int*   jt    = (const int*)d_in[1];
    const float* W1    = (const float*)d_in[2];
    const float* b1    = (const float*)d_in[3];
    const float* proto = (const float*)d_in[4];
    float* out = (float*)d_out;
    int write_T = (out_size >= N * KP + N * NSLOT) ? 1 : 0;

    p_hist<<<NBH, 256>>>(jt);
    p_scatter<<<NBH, 256>>>(jt);

    k_gemm1<<<dim3(N / 256, H / 128), 512>>>(emb, W1, b1);

    k_sinkhorn<<<NT * CSIZE, 256>>>(proto);

    if (write_T) k_out<<<(N * NSLOT / 4) / 256, 256>>>(jt, out);
    else         k_out_logits<<<(N * KP) / 256, 256>>>(jt, out);
}

// round 15
// speedup vs baseline: 1.0848x; 1.0848x over previous
#include <cuda_runtime.h>
#include <math.h>

#define N     8192
#define D     256
#define H     512
#define KP    64
#define NT    17
#define NSLOT (KP*NT)       // 1088
#define INV_TAU 20.0f
#define KLF  (1.0f/1.05f)
#define SITERS 50
#define CSIZE 8
#define MAXCHUNK 96
#define NBH   32            // histogram blocks (N/256)

// ---------------- scratch ----------------
__device__ float g_h[N*H];
__device__ float g_Mp[N*KP];      // M = -d2/tau, rows permuted by type
__device__ float g_up[N];
__device__ float g_lv[NT*KP];
__device__ int   g_start[NT+1];
__device__ int   g_perm[N];
__device__ int   g_pos[N];
__device__ int   g_bh[NBH*NT];    // per-block type histograms

// ---------------- packed f32x2 helpers (FFMA2: 2 FMA/lane/issue) ----------------
#define BCAST2(dst, x)     asm("mov.b64 %0, {%1, %1};" : "=l"(dst) : "f"(x))
#define FFMA2(c, a, b)     asm("fma.rn.f32x2 %0, %1, %2, %0;" : "+l"(c) : "l"(a), "l"(b))
#define UNPACK2(lo, hi, s) asm("mov.b64 {%0, %1}, %2;" : "=f"(lo), "=f"(hi) : "l"(s))

__device__ __forceinline__ unsigned smem_u32(const void* p) {
    unsigned a;
    asm("{ .reg .u64 t; cvta.to.shared.u64 t, %1; cvt.u32.u64 %0, t; }" : "=r"(a) : "l"(p));
    return a;
}

// ---------------- parallel stable counting sort (2 kernels) ---------------------
__global__ void p_hist(const int* __restrict__ jt) {
    __shared__ int h[8][NT];
    int tid = threadIdx.x, w = tid >> 5, lane = tid & 31, b = blockIdx.x;
    if (tid < 8 * NT) ((int*)h)[tid] = 0;
    __syncthreads();
    int t = jt[b * 256 + tid];
    unsigned mask = __match_any_sync(0xffffffffu, t);
    int rnk = __popc(mask & ((1u << lane) - 1u));
    if (rnk == 0) h[w][t] = __popc(mask);
    __syncthreads();
    if (tid < NT) {
        int s = 0;
#pragma unroll
        for (int ww = 0; ww < 8; ww++) s += h[ww][tid];
        g_bh[b * NT + tid] = s;
    }
}

__global__ void p_scatter(const int* __restrict__ jt) {
    __shared__ int cnt[NT];
    __shared__ int sstart[NT];
    __shared__ int soff[NT];
    __shared__ int h[8][NT];
    __shared__ int off[8][NT];
    int tid = threadIdx.x, w = tid >> 5, lane = tid & 31, b = blockIdx.x;
    if (tid < 8 * NT) ((int*)h)[tid] = 0;
    if (tid < NT) {
        int s = 0;
        for (int bb = 0; bb < NBH; bb++) s += g_bh[bb * NT + tid];
        cnt[tid] = s;
    }
    __syncthreads();
    if (tid == 0) {
        int s = 0;
        for (int t = 0; t < NT; t++) { sstart[t] = s; s += cnt[t]; }
        if (b == 0) {
            for (int t = 0; t < NT; t++) g_start[t] = sstart[t];
            g_start[NT] = s;
        }
    }
    __syncthreads();
    if (tid < NT) {
        int run = sstart[tid];
        for (int bb = 0; bb < b; bb++) run += g_bh[bb * NT + tid];
        soff[tid] = run;
    }
    int n = b * 256 + tid;
    int t = jt[n];
    unsigned mask = __match_any_sync(0xffffffffu, t);
    int rnk = __popc(mask & ((1u << lane) - 1u));
    if (rnk == 0) h[w][t] = __popc(mask);
    __syncthreads();
    if (tid < NT) {
        int run = soff[tid];
#pragma unroll
        for (int ww = 0; ww < 8; ww++) { off[ww][tid] = run; run += h[ww][tid]; }
    }
    __syncthreads();
    int pos = off[w][t] + rnk;
    g_perm[pos] = n;
    g_pos[n]  = pos;
}

// ---------------- GEMM1: h = selu(emb @ W1 + b1), f32x2 + sw pipeline -----------
__global__ void __launch_bounds__(512) k_gemm1(const float* __restrict__ A,
                                               const float* __restrict__ W,
                                               const float* __restrict__ bias) {
    __shared__ __align__(16) float As[16][260];   // k-major (row pairs adjacent)
    __shared__ __align__(16) float Bs[16][132];
    __shared__ float sb[128];
    int bm = blockIdx.x * 256, bn = blockIdx.y * 128;
    int tid = threadIdx.x;
    int w = tid >> 5, lane = tid & 31;
    int ty = ((w & 7) << 2) | (lane >> 3);   // 0..31
    int tx = ((w >> 3) << 3) | (lane & 7);   // 0..15
    if (tid < 128) sb[tid] = bias[bn + tid];

    int ar0 = tid >> 2,         ac4_0 = tid & 3;
    int ar1 = (tid + 512) >> 2, ac4_1 = tid & 3;
    int bk  = tid >> 5,         bn4   = tid & 31;

    unsigned long long acc[4][8];
#pragma unroll
    for (int i = 0; i < 4; i++)
#pragma unroll
        for (int j = 0; j < 8; j++) acc[i][j] = 0ULL;

    float4 pa0 = *(const float4*)&A[(bm + ar0) * D + ac4_0 * 4];
    float4 pa1 = *(const float4*)&A[(bm + ar1) * D + ac4_1 * 4];
    float4 pbv = *(const float4*)&W[bk * H + bn + bn4 * 4];

    for (int k0 = 0; k0 < D; k0 += 16) {
        As[ac4_0 * 4 + 0][ar0] = pa0.x; As[ac4_0 * 4 + 1][ar0] = pa0.y;
        As[ac4_0 * 4 + 2][ar0] = pa0.z; As[ac4_0 * 4 + 3][ar0] = pa0.w;
        As[ac4_1 * 4 + 0][ar1] = pa1.x; As[ac4_1 * 4 + 1][ar1] = pa1.y;
        As[ac4_1 * 4 + 2][ar1] = pa1.z; As[ac4_1 * 4 + 3][ar1] = pa1.w;
        *(float4*)&Bs[bk][bn4 * 4] = pbv;
        __syncthreads();

        if (k0 + 16 < D) {
            pa0 = *(const float4*)&A[(bm + ar0) * D + k0 + 16 + ac4_0 * 4];
            pa1 = *(const float4*)&A[(bm + ar1) * D + k0 + 16 + ac4_1 * 4];
            pbv = *(const float4*)&W[(k0 + 16 + bk) * H + bn + bn4 * 4];
        }

#pragma unroll
        for (int kk = 0; kk < 16; kk++) {
            ulonglong2 a01 = *(const ulonglong2*)&As[kk][ty * 8];
            ulonglong2 a23 = *(const ulonglong2*)&As[kk][ty * 8 + 4];
            float4 b0 = *(const float4*)&Bs[kk][tx * 8];
            float4 b1 = *(const float4*)&Bs[kk][tx * 8 + 4];
            unsigned long long ap[4] = {a01.x, a01.y, a23.x, a23.y};
            unsigned long long bb[8];
            float bf[8] = {b0.x, b0.y, b0.z, b0.w, b1.x, b1.y, b1.z, b1.w};
#pragma unroll
            for (int j = 0; j < 8; j++) BCAST2(bb[j], bf[j]);
#pragma unroll
            for (int pi = 0; pi < 4; pi++)
#pragma unroll
                for (int j = 0; j < 8; j++) FFMA2(acc[pi][j], ap[pi], bb[j]);
        }
        __syncthreads();
    }
    const float SC = 1.0507009873554805f;
    const float AL = 1.6732632423543772f;
#pragma unroll
    for (int pi = 0; pi < 4; pi++) {
        float o0[8], o1[8];
#pragma unroll
        for (int j = 0; j < 8; j++) {
            float x0, x1;
            UNPACK2(x0, x1, acc[pi][j]);
            x0 += sb[tx * 8 + j];
            x1 += sb[tx * 8 + j];
            o0[j] = (x0 > 0.f) ? SC * x0 : SC * AL * expm1f(x0);
            o1[j] = (x1 > 0.f) ? SC * x1 : SC * AL * expm1f(x1);
        }
        int row0 = bm + ty * 8 + pi * 2;
        *(float4*)&g_h[row0 * H + bn + tx * 8]           = make_float4(o0[0], o0[1], o0[2], o0[3]);
        *(float4*)&g_h[row0 * H + bn + tx * 8 + 4]       = make_float4(o0[4], o0[5], o0[6], o0[7]);
        *(float4*)&g_h[(row0 + 1) * H + bn + tx * 8]     = make_float4(o1[0], o1[1], o1[2], o1[3]);
        *(float4*)&g_h[(row0 + 1) * H + bn + tx * 8 + 4] = make_float4(o1[4], o1[5], o1[6], o1[7]);
    }
}

// ---------------- GEMM2: d2 -> M, f32x2 + sw pipeline, fused norms --------------
// BM=64, BN=64, BK=32, 256 threads; warp map 4 rows x 8 cols (R12-proven)
__global__ void __launch_bounds__(256) k_gemm2(const float* __restrict__ proto) {
    __shared__ __align__(16) float Hs[32][68];
    __shared__ __align__(16) float Ps[32][68];
    __shared__ float shn[64];
    __shared__ float spn[64];
    int bm = blockIdx.x * 64;
    int tid = threadIdx.x;
    int w = tid >> 5, lane = tid & 31;
    int rg = ((w & 3) << 2) | (lane >> 3);   // 0..15
    int cg = ((w >> 2) << 3) | (lane & 7);   // 0..15
    int lr = tid >> 3, lc = tid & 7;

    unsigned long long acc[2][4];
#pragma unroll
    for (int i = 0; i < 2; i++)
#pragma unroll
        for (int j = 0; j < 4; j++) acc[i][j] = 0ULL;
    float hn0 = 0.f, hn1 = 0.f, pn0 = 0.f, pn1 = 0.f;

    float4 sh0 = *(const float4*)&g_h[(bm + lr) * H + lc * 4];
    float4 sh1 = *(const float4*)&g_h[(bm + lr + 32) * H + lc * 4];
    float4 sp0 = *(const float4*)&proto[lr * H + lc * 4];
    float4 sp1 = *(const float4*)&proto[(lr + 32) * H + lc * 4];

    for (int j0 = 0; j0 < H; j0 += 32) {
        Hs[lc * 4 + 0][lr] = sh0.x; Hs[lc * 4 + 1][lr] = sh0.y;
        Hs[lc * 4 + 2][lr] = sh0.z; Hs[lc * 4 + 3][lr] = sh0.w;
        hn0 += sh0.x * sh0.x + sh0.y * sh0.y + sh0.z * sh0.z + sh0.w * sh0.w;
        Hs[lc * 4 + 0][lr + 32] = sh1.x; Hs[lc * 4 + 1][lr + 32] = sh1.y;
        Hs[lc * 4 + 2][lr + 32] = sh1.z; Hs[lc * 4 + 3][lr + 32] = sh1.w;
        hn1 += sh1.x * sh1.x + sh1.y * sh1.y + sh1.z * sh1.z + sh1.w * sh1.w;
        Ps[lc * 4 + 0][lr] = sp0.x; Ps[lc * 4 + 1][lr] = sp0.y;
        Ps[lc * 4 + 2][lr] = sp0.z; Ps[lc * 4 + 3][lr] = sp0.w;
        pn0 += sp0.x * sp0.x + sp0.y * sp0.y + sp0.z * sp0.z + sp0.w * sp0.w;
        Ps[lc * 4 + 0][lr + 32] = sp1.x; Ps[lc * 4 + 1][lr + 32] = sp1.y;
        Ps[lc * 4 + 2][lr + 32] = sp1.z; Ps[lc * 4 + 3][lr + 32] = sp1.w;
        pn1 += sp1.x * sp1.x + sp1.y * sp1.y + sp1.z * sp1.z + sp1.w * sp1.w;
        __syncthreads();

        if (j0 + 32 < H) {
            sh0 = *(const float4*)&g_h[(bm + lr) * H + j0 + 32 + lc * 4];
            sh1 = *(const float4*)&g_h[(bm + lr + 32) * H + j0 + 32 + lc * 4];
            sp0 = *(const float4*)&proto[lr * H + j0 + 32 + lc * 4];
            sp1 = *(const float4*)&proto[(lr + 32) * H + j0 + 32 + lc * 4];
        }

#pragma unroll
        for (int kk = 0; kk < 32; kk++) {
            ulonglong2 apair = *(const ulonglong2*)&Hs[kk][rg * 4];
            float4 b = *(const float4*)&Ps[kk][cg * 4];
            unsigned long long ap[2] = {apair.x, apair.y};
            unsigned long long bb[4];
            BCAST2(bb[0], b.x); BCAST2(bb[1], b.y);
            BCAST2(bb[2], b.z); BCAST2(bb[3], b.w);
#pragma unroll
            for (int pi = 0; pi < 2; pi++)
#pragma unroll
                for (int j = 0; j < 4; j++) FFMA2(acc[pi][j], ap[pi], bb[j]);
        }
        __syncthreads();
    }
#pragma unroll
    for (int o = 1; o < 8; o <<= 1) {
        hn0 += __shfl_xor_sync(0xffffffffu, hn0, o);
        hn1 += __shfl_xor_sync(0xffffffffu, hn1, o);
        pn0 += __shfl_xor_sync(0xffffffffu, pn0, o);
        pn1 += __shfl_xor_sync(0xffffffffu, pn1, o);
    }
    if (lc == 0) { shn[lr] = hn0; shn[lr + 32] = hn1; spn[lr] = pn0; spn[lr + 32] = pn1; }
    __syncthreads();

#pragma unroll
    for (int pi = 0; pi < 2; pi++) {
        float c0[4], c1[4];
#pragma unroll
        for (int j = 0; j < 4; j++) UNPACK2(c0[j], c1[j], acc[pi][j]);
        int n0 = bm + rg * 4 + pi * 2;
        float hnA = shn[rg * 4 + pi * 2], hnB = shn[rg * 4 + pi * 2 + 1];
        int pA = g_pos[n0], pB = g_pos[n0 + 1];
        float oA[4], oB[4];
#pragma unroll
        for (int j = 0; j < 4; j++) {
            float pn = spn[cg * 4 + j];
            oA[j] = -INV_TAU * fmaxf(hnA + pn - 2.f * c0[j], 0.f);
            oB[j] = -INV_TAU * fmaxf(hnB + pn - 2.f * c1[j], 0.f);
        }
        *(float4*)&g_Mp[pA * KP + cg * 4] = make_float4(oA[0], oA[1], oA[2], oA[3]);
        *(float4*)&g_Mp[pB * KP + cg * 4] = make_float4(oB[0], oB[1], oB[2], oB[3]);
    }
}

// ---------------- Sinkhorn: 17 types x 8-CTA clusters, PUSH-based combine -------
// Remote partials delivered by fire-and-forget st.shared::cluster (issue-only)
// instead of 16 serialized 215-cyc DSMEM loads per iteration.
__global__ void __cluster_dims__(CSIZE, 1, 1) __launch_bounds__(256)
k_sinkhorn() {
    __shared__ __align__(16) float sM[MAXCHUNK * 65];
    __shared__ float su[MAXCHUNK];
    __shared__ float slv[KP];
    __shared__ float wmx[4][KP], wse[4][KP];
    __shared__ __align__(8) unsigned long long pall[2][CSIZE][KP];  // packed (mx,se)

    int t    = blockIdx.x >> 3;
    int rank = blockIdx.x & 7;
    int s = g_start[t];
    int c = g_start[t + 1] - s;
    int chunk = (c + CSIZE - 1) >> 3;
    int r0 = rank * chunk;
    int cn = c - r0;
    if (cn < 0) cn = 0;
    if (cn > chunk) cn = chunk;
    int tid = threadIdx.x, w = tid >> 5, lane = tid & 31;

    for (int idx = tid; idx < cn * KP; idx += 256) {
        int r = idx >> 6, col = idx & 63;
        sM[r * 65 + col] = g_Mp[(s + r0 + r) * KP + col];
    }
    if (tid < KP) slv[tid] = 0.f;
    __syncthreads();

    int q = (cn + 3) >> 2;
    int sub = tid & 3;
    unsigned gmask = 0xFu << (tid & 28);
    int col = ((w & 1) << 5) + lane;
    int rs_ = (w >> 1) * q;
    int re_ = min(cn, rs_ + q);
    int nr  = re_ - rs_;

    // precompute peer addresses for this thread's pall slots (both parities)
    unsigned pdst0[CSIZE], pdst1[CSIZE];
    if (tid < KP) {
        unsigned l0 = smem_u32(&pall[0][rank][tid]);
        unsigned l1 = smem_u32(&pall[1][rank][tid]);
#pragma unroll
        for (int rk = 0; rk < CSIZE; rk++) {
            asm("mapa.shared::cluster.u32 %0, %1, %2;" : "=r"(pdst0[rk]) : "r"(l0), "r"(rk));
            asm("mapa.shared::cluster.u32 %0, %1, %2;" : "=r"(pdst1[rk]) : "r"(l1), "r"(rk));
        }
    }

    for (int it = 0; it < SITERS; it++) {
        // ---- row update: 4 threads/row, 4-way interleaved accumulators
        float lvr[16];
#pragma unroll
        for (int j = 0; j < 16; j++) lvr[j] = slv[sub * 16 + j];
        for (int r = tid >> 2; r < cn; r += 64) {
            const float* row = &sM[r * 65 + sub * 16];
            float v[16];
            float m0 = -3.4e38f, m1 = -3.4e38f, m2 = -3.4e38f, m3 = -3.4e38f;
#pragma unroll
            for (int j = 0; j < 16; j += 4) {
                v[j]   = row[j]   + lvr[j];   m0 = fmaxf(m0, v[j]);
                v[j+1] = row[j+1] + lvr[j+1]; m1 = fmaxf(m1, v[j+1]);
                v[j+2] = row[j+2] + lvr[j+2]; m2 = fmaxf(m2, v[j+2]);
                v[j+3] = row[j+3] + lvr[j+3]; m3 = fmaxf(m3, v[j+3]);
            }
            float mx = fmaxf(fmaxf(m0, m1), fmaxf(m2, m3));
            mx = fmaxf(mx, __shfl_xor_sync(gmask, mx, 1));
            mx = fmaxf(mx, __shfl_xor_sync(gmask, mx, 2));
            float s0 = 0.f, s1 = 0.f, s2 = 0.f, s3 = 0.f;
#pragma unroll
            for (int j = 0; j < 16; j += 4) {
                s0 += __expf(v[j]   - mx);
                s1 += __expf(v[j+1] - mx);
                s2 += __expf(v[j+2] - mx);
                s3 += __expf(v[j+3] - mx);
            }
            float se = (s0 + s1) + (s2 + s3);
            se += __shfl_xor_sync(gmask, se, 1);
            se += __shfl_xor_sync(gmask, se, 2);
            if (sub == 0) su[r] = -(mx + __logf(se));
        }
        __syncthreads();

        // ---- column partials: value-cached, 4-way interleaved accumulators
        {
            float v[24];
            float m0 = -3.4e38f, m1 = -3.4e38f, m2 = -3.4e38f, m3 = -3.4e38f;
#pragma unroll
            for (int i = 0; i < 24; i++) {
                if (i >= nr) break;
                v[i] = sM[(rs_ + i) * 65 + col] + su[rs_ + i];
                if ((i & 3) == 0) m0 = fmaxf(m0, v[i]);
                else if ((i & 3) == 1) m1 = fmaxf(m1, v[i]);
                else if ((i & 3) == 2) m2 = fmaxf(m2, v[i]);
                else m3 = fmaxf(m3, v[i]);
            }
            float mx = fmaxf(fmaxf(m0, m1), fmaxf(m2, m3));
            float s0 = 0.f, s1 = 0.f, s2 = 0.f, s3 = 0.f;
#pragma unroll
            for (int i = 0; i < 24; i++) {
                if (i >= nr) break;
                float e = __expf(v[i] - mx);
                if ((i & 3) == 0) s0 += e;
                else if ((i & 3) == 1) s1 += e;
                else if ((i & 3) == 2) s2 += e;
                else s3 += e;
            }
            wmx[w >> 1][col] = mx;
            wse[w >> 1][col] = (s0 + s1) + (s2 + s3);
        }
        __syncthreads();
        int par = it & 1;
        if (tid < KP) {
            float mx = fmaxf(fmaxf(wmx[0][tid], wmx[1][tid]), fmaxf(wmx[2][tid], wmx[3][tid]));
            float se = 0.f;
#pragma unroll
            for (int i = 0; i < 4; i++) se += wse[i][tid] * __expf(wmx[i][tid] - mx);
            // PUSH packed partial to the same slot in all 8 cluster CTAs
            unsigned long long pv;
            asm("mov.b64 %0, {%1, %2};" : "=l"(pv) : "f"(mx), "f"(se));
            const unsigned* pd = par ? pdst1 : pdst0;
#pragma unroll
            for (int rk = 0; rk < CSIZE; rk++)
                asm volatile("st.shared::cluster.b64 [%0], %1;" :: "r"(pd[rk]), "l"(pv) : "memory");
        }

        // arrive=release orders the remote stores; wait=acquire makes them visible
        asm volatile("barrier.cluster.arrive.aligned;" ::: "memory");
        asm volatile("barrier.cluster.wait.aligned;" ::: "memory");

        if (tid < KP) {
            float m[CSIZE], sv[CSIZE];
            float MX = -3.4e38f;
#pragma unroll
            for (int rk = 0; rk < CSIZE; rk++) {
                unsigned long long pv = pall[par][rk][tid];    // LOCAL smem read
                UNPACK2(m[rk], sv[rk], pv);
                MX = fmaxf(MX, m[rk]);
            }
            float SE = 0.f;
#pragma unroll
            for (int rk = 0; rk < CSIZE; rk++) SE += sv[rk] * __expf(m[rk] - MX);
            slv[tid] = -KLF * (MX + __logf(SE));
        }
        __syncthreads();
    }

    if (tid < cn) g_up[s + r0 + tid] = su[tid];
    if (rank == 0 && tid < KP) g_lv[t * KP + tid] = slv[tid];

    // final cluster barrier: orders the last remote stores before any CTA exits
    asm volatile("barrier.cluster.arrive.aligned;" ::: "memory");
    asm volatile("barrier.cluster.wait.aligned;" ::: "memory");
}

// ---------------- fused output: T (float4 coalesced) + logits -------------------
__global__ void k_out(const int* __restrict__ jt, float* __restrict__ out) {
    int idx4 = blockIdx.x * blockDim.x + threadIdx.x;   // over N*NSLOT/4
    int base = idx4 * 4;
    int n = base / NSLOT;
    int s0 = base - n * NSLOT;
    int tn = jt[n];
    int p = g_pos[n];
    float up = g_up[p];
    float e[4] = {0.f, 0.f, 0.f, 0.f};
#pragma unroll
    for (int q = 0; q < 4; q++) {
        int slot = s0 + q;
        int k = slot / NT;
        int t = slot - k * NT;
        if (t == tn) {
            float ev = __expf(g_Mp[p * KP + k] + up + g_lv[tn * KP + k]);
            e[q] = ev;
            out[n * KP + k] = __logf(ev + 1e-8f);
        }
    }
    *(float4*)&out[N * KP + base] = make_float4(e[0], e[1], e[2], e[3]);
}

__global__ void k_out_logits(const int* __restrict__ jt, float* __restrict__ out) {
    int idx = blockIdx.x * blockDim.x + threadIdx.x;   // over N*KP
    if (idx >= N * KP) return;
    int n = idx >> 6, k = idx & 63;
    int tn = jt[n];
    int p = g_pos[n];
    float e = __expf(g_Mp[p * KP + k] + g_up[p] + g_lv[tn * KP + k]);
    out[n * KP + k] = __logf(e + 1e-8f);
}

// ---------------- launch --------------------------------------------------------
extern "C" void kernel_launch(void* const* d_in, const int* in_sizes, int n_in,
                              void* d_out, int out_size) {
    const float* emb   = (const float*)d_in[0];
    const int*   jt    = (const int*)d_in[1];
    const float* W1    = (const float*)d_in[2];
    const float* b1    = (const float*)d_in[3];
    const float* proto = (const float*)d_in[4];
    float* out = (float*)d_out;
    int write_T = (out_size >= N * KP + N * NSLOT) ? 1 : 0;

    p_hist<<<NBH, 256>>>(jt);
    p_scatter<<<NBH, 256>>>(jt);

    k_gemm1<<<dim3(N / 256, H / 128), 512>>>(emb, W1, b1);
    k_gemm2<<<N / 64, 256>>>(proto);

    k_sinkhorn<<<NT * CSIZE, 256>>>();

    if (write_T) k_out<<<(N * NSLOT / 4) / 256, 256>>>(jt, out);
    else         k_out_logits<<<(N * KP) / 256, 256>>>(jt, out);
}

// round 16
// speedup vs baseline: 1.2387x; 1.1419x over previous
#include <cuda_runtime.h>
#include <math.h>

#define N     8192
#define D     256
#define H     512
#define KP    64
#define NT    17
#define NSLOT (KP*NT)       // 1088
#define INV_TAU 20.0f
#define KLF  (1.0f/1.05f)
#define SITERS 50
#define CSIZE 8
#define MAXCHUNK 96
#define NBH   32            // histogram blocks (N/256)

// ---------------- scratch ----------------
__device__ float g_h[N*H];
__device__ float g_Mp[N*KP];      // M = -d2/tau, rows permuted by type
__device__ float g_up[N];
__device__ float g_lv[NT*KP];
__device__ int   g_start[NT+1];
__device__ int   g_perm[N];
__device__ int   g_pos[N];
__device__ int   g_bh[NBH*NT];    // per-block type histograms

// ---------------- packed f32x2 helpers (FFMA2: 2 FMA/lane/issue) ----------------
#define BCAST2(dst, x)     asm("mov.b64 %0, {%1, %1};" : "=l"(dst) : "f"(x))
#define FFMA2(c, a, b)     asm("fma.rn.f32x2 %0, %1, %2, %0;" : "+l"(c) : "l"(a), "l"(b))
#define UNPACK2(lo, hi, s) asm("mov.b64 {%0, %1}, %2;" : "=f"(lo), "=f"(hi) : "l"(s))

__device__ __forceinline__ unsigned smem_u32(const void* p) {
    unsigned a;
    asm("{ .reg .u64 t; cvta.to.shared.u64 t, %1; cvt.u32.u64 %0, t; }" : "=r"(a) : "l"(p));
    return a;
}

// ---------------- parallel stable counting sort (2 kernels) ---------------------
__global__ void p_hist(const int* __restrict__ jt) {
    __shared__ int h[8][NT];
    int tid = threadIdx.x, w = tid >> 5, lane = tid & 31, b = blockIdx.x;
    if (tid < 8 * NT) ((int*)h)[tid] = 0;
    __syncthreads();
    int t = jt[b * 256 + tid];
    unsigned mask = __match_any_sync(0xffffffffu, t);
    int rnk = __popc(mask & ((1u << lane) - 1u));
    if (rnk == 0) h[w][t] = __popc(mask);
    __syncthreads();
    if (tid < NT) {
        int s = 0;
#pragma unroll
        for (int ww = 0; ww < 8; ww++) s += h[ww][tid];
        g_bh[b * NT + tid] = s;
    }
}

__global__ void p_scatter(const int* __restrict__ jt) {
    __shared__ int cnt[NT];
    __shared__ int sstart[NT];
    __shared__ int soff[NT];
    __shared__ int h[8][NT];
    __shared__ int off[8][NT];
    int tid = threadIdx.x, w = tid >> 5, lane = tid & 31, b = blockIdx.x;
    if (tid < 8 * NT) ((int*)h)[tid] = 0;
    if (tid < NT) {
        int s = 0;
        for (int bb = 0; bb < NBH; bb++) s += g_bh[bb * NT + tid];
        cnt[tid] = s;
    }
    __syncthreads();
    if (tid == 0) {
        int s = 0;
        for (int t = 0; t < NT; t++) { sstart[t] = s; s += cnt[t]; }
        if (b == 0) {
            for (int t = 0; t < NT; t++) g_start[t] = sstart[t];
            g_start[NT] = s;
        }
    }
    __syncthreads();
    if (tid < NT) {
        int run = sstart[tid];
        for (int bb = 0; bb < b; bb++) run += g_bh[bb * NT + tid];
        soff[tid] = run;
    }
    int n = b * 256 + tid;
    int t = jt[n];
    unsigned mask = __match_any_sync(0xffffffffu, t);
    int rnk = __popc(mask & ((1u << lane) - 1u));
    if (rnk == 0) h[w][t] = __popc(mask);
    __syncthreads();
    if (tid < NT) {
        int run = soff[tid];
#pragma unroll
        for (int ww = 0; ww < 8; ww++) { off[ww][tid] = run; run += h[ww][tid]; }
    }
    __syncthreads();
    int pos = off[w][t] + rnk;
    g_perm[pos] = n;
    g_pos[n]  = pos;
}

// ---------------- GEMM1: h = selu(emb @ W1 + b1), f32x2 + sw pipeline -----------
__global__ void __launch_bounds__(512) k_gemm1(const float* __restrict__ A,
                                               const float* __restrict__ W,
                                               const float* __restrict__ bias) {
    __shared__ __align__(16) float As[16][260];
    __shared__ __align__(16) float Bs[16][132];
    __shared__ float sb[128];
    int bm = blockIdx.x * 256, bn = blockIdx.y * 128;
    int tid = threadIdx.x;
    int w = tid >> 5, lane = tid & 31;
    int ty = ((w & 7) << 2) | (lane >> 3);
    int tx = ((w >> 3) << 3) | (lane & 7);
    if (tid < 128) sb[tid] = bias[bn + tid];

    int ar0 = tid >> 2,         ac4_0 = tid & 3;
    int ar1 = (tid + 512) >> 2, ac4_1 = tid & 3;
    int bk  = tid >> 5,         bn4   = tid & 31;

    unsigned long long acc[4][8];
#pragma unroll
    for (int i = 0; i < 4; i++)
#pragma unroll
        for (int j = 0; j < 8; j++) acc[i][j] = 0ULL;

    float4 pa0 = *(const float4*)&A[(bm + ar0) * D + ac4_0 * 4];
    float4 pa1 = *(const float4*)&A[(bm + ar1) * D + ac4_1 * 4];
    float4 pbv = *(const float4*)&W[bk * H + bn + bn4 * 4];

    for (int k0 = 0; k0 < D; k0 += 16) {
        As[ac4_0 * 4 + 0][ar0] = pa0.x; As[ac4_0 * 4 + 1][ar0] = pa0.y;
        As[ac4_0 * 4 + 2][ar0] = pa0.z; As[ac4_0 * 4 + 3][ar0] = pa0.w;
        As[ac4_1 * 4 + 0][ar1] = pa1.x; As[ac4_1 * 4 + 1][ar1] = pa1.y;
        As[ac4_1 * 4 + 2][ar1] = pa1.z; As[ac4_1 * 4 + 3][ar1] = pa1.w;
        *(float4*)&Bs[bk][bn4 * 4] = pbv;
        __syncthreads();

        if (k0 + 16 < D) {
            pa0 = *(const float4*)&A[(bm + ar0) * D + k0 + 16 + ac4_0 * 4];
            pa1 = *(const float4*)&A[(bm + ar1) * D + k0 + 16 + ac4_1 * 4];
            pbv = *(const float4*)&W[(k0 + 16 + bk) * H + bn + bn4 * 4];
        }

#pragma unroll
        for (int kk = 0; kk < 16; kk++) {
            ulonglong2 a01 = *(const ulonglong2*)&As[kk][ty * 8];
            ulonglong2 a23 = *(const ulonglong2*)&As[kk][ty * 8 + 4];
            float4 b0 = *(const float4*)&Bs[kk][tx * 8];
            float4 b1 = *(const float4*)&Bs[kk][tx * 8 + 4];
            unsigned long long ap[4] = {a01.x, a01.y, a23.x, a23.y};
            unsigned long long bb[8];
            float bf[8] = {b0.x, b0.y, b0.z, b0.w, b1.x, b1.y, b1.z, b1.w};
#pragma unroll
            for (int j = 0; j < 8; j++) BCAST2(bb[j], bf[j]);
#pragma unroll
            for (int pi = 0; pi < 4; pi++)
#pragma unroll
                for (int j = 0; j < 8; j++) FFMA2(acc[pi][j], ap[pi], bb[j]);
        }
        __syncthreads();
    }
    const float SC = 1.0507009873554805f;
    const float AL = 1.6732632423543772f;
#pragma unroll
    for (int pi = 0; pi < 4; pi++) {
        float o0[8], o1[8];
#pragma unroll
        for (int j = 0; j < 8; j++) {
            float x0, x1;
            UNPACK2(x0, x1, acc[pi][j]);
            x0 += sb[tx * 8 + j];
            x1 += sb[tx * 8 + j];
            o0[j] = (x0 > 0.f) ? SC * x0 : SC * AL * expm1f(x0);
            o1[j] = (x1 > 0.f) ? SC * x1 : SC * AL * expm1f(x1);
        }
        int row0 = bm + ty * 8 + pi * 2;
        *(float4*)&g_h[row0 * H + bn + tx * 8]           = make_float4(o0[0], o0[1], o0[2], o0[3]);
        *(float4*)&g_h[row0 * H + bn + tx * 8 + 4]       = make_float4(o0[4], o0[5], o0[6], o0[7]);
        *(float4*)&g_h[(row0 + 1) * H + bn + tx * 8]     = make_float4(o1[0], o1[1], o1[2], o1[3]);
        *(float4*)&g_h[(row0 + 1) * H + bn + tx * 8 + 4] = make_float4(o1[4], o1[5], o1[6], o1[7]);
    }
}

// ---------------- GEMM2: d2 -> M, f32x2 + sw pipeline, fused norms --------------
__global__ void __launch_bounds__(256) k_gemm2(const float* __restrict__ proto) {
    __shared__ __align__(16) float Hs[32][68];
    __shared__ __align__(16) float Ps[32][68];
    __shared__ float shn[64];
    __shared__ float spn[64];
    int bm = blockIdx.x * 64;
    int tid = threadIdx.x;
    int w = tid >> 5, lane = tid & 31;
    int rg = ((w & 3) << 2) | (lane >> 3);
    int cg = ((w >> 2) << 3) | (lane & 7);
    int lr = tid >> 3, lc = tid & 7;

    unsigned long long acc[2][4];
#pragma unroll
    for (int i = 0; i < 2; i++)
#pragma unroll
        for (int j = 0; j < 4; j++) acc[i][j] = 0ULL;
    float hn0 = 0.f, hn1 = 0.f, pn0 = 0.f, pn1 = 0.f;

    float4 sh0 = *(const float4*)&g_h[(bm + lr) * H + lc * 4];
    float4 sh1 = *(const float4*)&g_h[(bm + lr + 32) * H + lc * 4];
    float4 sp0 = *(const float4*)&proto[lr * H + lc * 4];
    float4 sp1 = *(const float4*)&proto[(lr + 32) * H + lc * 4];

    for (int j0 = 0; j0 < H; j0 += 32) {
        Hs[lc * 4 + 0][lr] = sh0.x; Hs[lc * 4 + 1][lr] = sh0.y;
        Hs[lc * 4 + 2][lr] = sh0.z; Hs[lc * 4 + 3][lr] = sh0.w;
        hn0 += sh0.x * sh0.x + sh0.y * sh0.y + sh0.z * sh0.z + sh0.w * sh0.w;
        Hs[lc * 4 + 0][lr + 32] = sh1.x; Hs[lc * 4 + 1][lr + 32] = sh1.y;
        Hs[lc * 4 + 2][lr + 32] = sh1.z; Hs[lc * 4 + 3][lr + 32] = sh1.w;
        hn1 += sh1.x * sh1.x + sh1.y * sh1.y + sh1.z * sh1.z + sh1.w * sh1.w;
        Ps[lc * 4 + 0][lr] = sp0.x; Ps[lc * 4 + 1][lr] = sp0.y;
        Ps[lc * 4 + 2][lr] = sp0.z; Ps[lc * 4 + 3][lr] = sp0.w;
        pn0 += sp0.x * sp0.x + sp0.y * sp0.y + sp0.z * sp0.z + sp0.w * sp0.w;
        Ps[lc * 4 + 0][lr + 32] = sp1.x; Ps[lc * 4 + 1][lr + 32] = sp1.y;
        Ps[lc * 4 + 2][lr + 32] = sp1.z; Ps[lc * 4 + 3][lr + 32] = sp1.w;
        pn1 += sp1.x * sp1.x + sp1.y * sp1.y + sp1.z * sp1.z + sp1.w * sp1.w;
        __syncthreads();

        if (j0 + 32 < H) {
            sh0 = *(const float4*)&g_h[(bm + lr) * H + j0 + 32 + lc * 4];
            sh1 = *(const float4*)&g_h[(bm + lr + 32) * H + j0 + 32 + lc * 4];
            sp0 = *(const float4*)&proto[lr * H + j0 + 32 + lc * 4];
            sp1 = *(const float4*)&proto[(lr + 32) * H + j0 + 32 + lc * 4];
        }

#pragma unroll
        for (int kk = 0; kk < 32; kk++) {
            ulonglong2 apair = *(const ulonglong2*)&Hs[kk][rg * 4];
            float4 b = *(const float4*)&Ps[kk][cg * 4];
            unsigned long long ap[2] = {apair.x, apair.y};
            unsigned long long bb[4];
            BCAST2(bb[0], b.x); BCAST2(bb[1], b.y);
            BCAST2(bb[2], b.z); BCAST2(bb[3], b.w);
#pragma unroll
            for (int pi = 0; pi < 2; pi++)
#pragma unroll
                for (int j = 0; j < 4; j++) FFMA2(acc[pi][j], ap[pi], bb[j]);
        }
        __syncthreads();
    }
#pragma unroll
    for (int o = 1; o < 8; o <<= 1) {
        hn0 += __shfl_xor_sync(0xffffffffu, hn0, o);
        hn1 += __shfl_xor_sync(0xffffffffu, hn1, o);
        pn0 += __shfl_xor_sync(0xffffffffu, pn0, o);
        pn1 += __shfl_xor_sync(0xffffffffu, pn1, o);
    }
    if (lc == 0) { shn[lr] = hn0; shn[lr + 32] = hn1; spn[lr] = pn0; spn[lr + 32] = pn1; }
    __syncthreads();

#pragma unroll
    for (int pi = 0; pi < 2; pi++) {
        float c0[4], c1[4];
#pragma unroll
        for (int j = 0; j < 4; j++) UNPACK2(c0[j], c1[j], acc[pi][j]);
        int n0 = bm + rg * 4 + pi * 2;
        float hnA = shn[rg * 4 + pi * 2], hnB = shn[rg * 4 + pi * 2 + 1];
        int pA = g_pos[n0], pB = g_pos[n0 + 1];
        float oA[4], oB[4];
#pragma unroll
        for (int j = 0; j < 4; j++) {
            float pn = spn[cg * 4 + j];
            oA[j] = -INV_TAU * fmaxf(hnA + pn - 2.f * c0[j], 0.f);
            oB[j] = -INV_TAU * fmaxf(hnB + pn - 2.f * c1[j], 0.f);
        }
        *(float4*)&g_Mp[pA * KP + cg * 4] = make_float4(oA[0], oA[1], oA[2], oA[3]);
        *(float4*)&g_Mp[pB * KP + cg * 4] = make_float4(oB[0], oB[1], oB[2], oB[3]);
    }
}

// ---------------- Sinkhorn: single-pass iterations (no column pass) -------------
// Identity: lse_col(M+u) = log(Sum_r E[r,k]/se_r) - lv[k], with E/se from the row
// pass. Q in [0,1] => column sums need no max protection. Per iter: row pass
// (exp) + warp butterfly Q-sum + smem reduce + push float partial + barrier +
// lv = KLF*(lv - log S). Half the MUFU, no col scan, one less syncthreads.
__global__ void __cluster_dims__(CSIZE, 1, 1) __launch_bounds__(256)
k_sinkhorn() {
    __shared__ __align__(16) float sM[MAXCHUNK * 65];
    __shared__ float su[MAXCHUNK];
    __shared__ __align__(16) float slv[KP];
    __shared__ float wq[8][KP];                     // per-warp column partials
    __shared__ float pall[2][CSIZE][KP];            // pushed rank partials

    int t    = blockIdx.x >> 3;
    int rank = blockIdx.x & 7;
    int s = g_start[t];
    int c = g_start[t + 1] - s;
    int chunk = (c + CSIZE - 1) >> 3;
    int r0 = rank * chunk;
    int cn = c - r0;
    if (cn < 0) cn = 0;
    if (cn > chunk) cn = chunk;
    if (cn > MAXCHUNK) cn = MAXCHUNK;
    int tid = threadIdx.x, w = tid >> 5, lane = tid & 31;
    int g = tid >> 2, sub = tid & 3;
    unsigned gmask = 0xFu << (lane & 28);

    for (int idx = tid; idx < cn * KP; idx += 256) {
        int r = idx >> 6, col = idx & 63;
        sM[r * 65 + col] = g_Mp[(s + r0 + r) * KP + col];
    }
    if (tid < KP) slv[tid] = 0.f;
    __syncthreads();

    // peer addresses for the float partial push (both parities)
    unsigned pd0[CSIZE], pd1[CSIZE];
    if (tid < KP) {
        unsigned l0 = smem_u32(&pall[0][rank][tid]);
        unsigned l1 = smem_u32(&pall[1][rank][tid]);
#pragma unroll
        for (int rk = 0; rk < CSIZE; rk++) {
            asm("mapa.shared::cluster.u32 %0, %1, %2;" : "=r"(pd0[rk]) : "r"(l0), "r"(rk));
            asm("mapa.shared::cluster.u32 %0, %1, %2;" : "=r"(pd1[rk]) : "r"(l1), "r"(rk));
        }
    }

    for (int it = 0; it < SITERS; it++) {
        int par = it & 1;
        // ---- row pass: lse + Q accumulation (4 threads/row, 16 cols each)
        float lvr[16];
#pragma unroll
        for (int j = 0; j < 16; j++) lvr[j] = slv[sub * 16 + j];
        float qacc[16];
#pragma unroll
        for (int j = 0; j < 16; j++) qacc[j] = 0.f;

        for (int r = g; r < cn; r += 64) {
            const float* row = &sM[r * 65 + sub * 16];
            float v[16];
            float m0 = -3.4e38f, m1 = -3.4e38f, m2 = -3.4e38f, m3 = -3.4e38f;
#pragma unroll
            for (int j = 0; j < 16; j += 4) {
                v[j]   = row[j]   + lvr[j];   m0 = fmaxf(m0, v[j]);
                v[j+1] = row[j+1] + lvr[j+1]; m1 = fmaxf(m1, v[j+1]);
                v[j+2] = row[j+2] + lvr[j+2]; m2 = fmaxf(m2, v[j+2]);
                v[j+3] = row[j+3] + lvr[j+3]; m3 = fmaxf(m3, v[j+3]);
            }
            float mx = fmaxf(fmaxf(m0, m1), fmaxf(m2, m3));
            mx = fmaxf(mx, __shfl_xor_sync(gmask, mx, 1));
            mx = fmaxf(mx, __shfl_xor_sync(gmask, mx, 2));
            float e[16];
            float s0 = 0.f, s1 = 0.f, s2 = 0.f, s3 = 0.f;
#pragma unroll
            for (int j = 0; j < 16; j += 4) {
                e[j]   = __expf(v[j]   - mx); s0 += e[j];
                e[j+1] = __expf(v[j+1] - mx); s1 += e[j+1];
                e[j+2] = __expf(v[j+2] - mx); s2 += e[j+2];
                e[j+3] = __expf(v[j+3] - mx); s3 += e[j+3];
            }
            float se = (s0 + s1) + (s2 + s3);
            se += __shfl_xor_sync(gmask, se, 1);
            se += __shfl_xor_sync(gmask, se, 2);
            float rinv = __fdividef(1.f, se);
#pragma unroll
            for (int j = 0; j < 16; j++) qacc[j] += e[j] * rinv;
            if (it == SITERS - 1 && sub == 0) su[r] = -(mx + __logf(se));
        }

        // ---- butterfly Q across the 8 row-lanes of each warp (all lanes)
#pragma unroll
        for (int st = 4; st <= 16; st <<= 1)
#pragma unroll
            for (int j = 0; j < 16; j++)
                qacc[j] += __shfl_xor_sync(0xffffffffu, qacc[j], st);
        if (lane < 4)
#pragma unroll
            for (int j = 0; j < 16; j++) wq[w][lane * 16 + j] = qacc[j];
        __syncthreads();

        // ---- reduce 8 warps, push float partial to all ranks
        if (tid < KP) {
            float Sl = 0.f;
#pragma unroll
            for (int ww = 0; ww < 8; ww++) Sl += wq[ww][tid];
            const unsigned* pd = par ? pd1 : pd0;
#pragma unroll
            for (int rk = 0; rk < CSIZE; rk++)
                asm volatile("st.shared::cluster.f32 [%0], %1;" :: "r"(pd[rk]), "f"(Sl) : "memory");
        }

        asm volatile("barrier.cluster.arrive.aligned;" ::: "memory");
        asm volatile("barrier.cluster.wait.aligned;" ::: "memory");

        // ---- lv update: lv = KLF*(lv - log S)
        if (tid < KP) {
            float S = 0.f;
#pragma unroll
            for (int rk = 0; rk < CSIZE; rk++) S += pall[par][rk][tid];
            S = fmaxf(S, 1e-35f);
            slv[tid] = KLF * (slv[tid] - __logf(S));
        }
        __syncthreads();
    }

    if (tid < cn) g_up[s + r0 + tid] = su[tid];
    if (rank == 0 && tid < KP) g_lv[t * KP + tid] = slv[tid];

    // final cluster barrier: orders the last remote stores before any CTA exits
    asm volatile("barrier.cluster.arrive.aligned;" ::: "memory");
    asm volatile("barrier.cluster.wait.aligned;" ::: "memory");
}

// ---------------- fused output: T (float4 coalesced) + logits -------------------
__global__ void k_out(const int* __restrict__ jt, float* __restrict__ out) {
    int idx4 = blockIdx.x * blockDim.x + threadIdx.x;   // over N*NSLOT/4
    int base = idx4 * 4;
    int n = base / NSLOT;
    int s0 = base - n * NSLOT;
    int tn = jt[n];
    int p = g_pos[n];
    float up = g_up[p];
    float e[4] = {0.f, 0.f, 0.f, 0.f};
#pragma unroll
    for (int q = 0; q < 4; q++) {
        int slot = s0 + q;
        int k = slot / NT;
        int t = slot - k * NT;
        if (t == tn) {
            float ev = __expf(g_Mp[p * KP + k] + up + g_lv[tn * KP + k]);
            e[q] = ev;
            out[n * KP + k] = __logf(ev + 1e-8f);
        }
    }
    *(float4*)&out[N * KP + base] = make_float4(e[0], e[1], e[2], e[3]);
}

__global__ void k_out_logits(const int* __restrict__ jt, float* __restrict__ out) {
    int idx = blockIdx.x * blockDim.x + threadIdx.x;   // over N*KP
    if (idx >= N * KP) return;
    int n = idx >> 6, k = idx & 63;
    int tn = jt[n];
    int p = g_pos[n];
    float e = __expf(g_Mp[p * KP + k] + g_up[p] + g_lv[tn * KP + k]);
    out[n * KP + k] = __logf(e + 1e-8f);
}

// ---------------- launch --------------------------------------------------------
extern "C" void kernel_launch(void* const* d_in, const int* in_sizes, int n_in,
                              void* d_out, int out_size) {
    const float* emb   = (const float*)d_in[0];
    const int*   jt    = (const int*)d_in[1];
    const float* W1    = (const float*)d_in[2];
    const float* b1    = (const float*)d_in[3];
    const float* proto = (const float*)d_in[4];
    float* out = (float*)d_out;
    int write_T = (out_size >= N * KP + N * NSLOT) ? 1 : 0;

    p_hist<<<NBH, 256>>>(jt);
    p_scatter<<<NBH, 256>>>(jt);

    k_gemm1<<<dim3(N / 256, H / 128), 512>>>(emb, W1, b1);
    k_gemm2<<<N / 64, 256>>>(proto);

    k_sinkhorn<<<NT * CSIZE, 256>>>();

    if (write_T) k_out<<<(N * NSLOT / 4) / 256, 256>>>(jt, out);
    else         k_out_logits<<<(N * KP) / 256, 256>>>(jt, out);
}